// round 13
// baseline (speedup 1.0000x reference)
#include <cuda_runtime.h>
#include <cuda_bf16.h>
#include <cstdint>

// Problem constants (fixed by dataset)
#define DDIM 256
#define CODES 1024
#define BM   128          // rows per CTA
#define BN   128          // codes per chunk
#define NCHUNK 8
#define MARGIN 2e-3f
#define TIE_ULPS 2
#define FILT_EPS 4e-3f

// dynamic smem layout (bytes)
#define SM_CN     0          // 1024 f32          (4096)
#define SM_BIDX   4096       // 128 int           (512)
#define SM_A_H    8192       // 128 rows x 528B   (67584)
#define SM_A_L    75776      // 128 rows x 528B   (67584)
#define SM_B      143360     // 2 stages x 2 mats x 128 x 144B (73728)
#define SM_TOTAL  217088
#define A_STRIDE  528        // 256 bf16 + 8 pad elems
#define B_STRIDE  144        // 64 bf16 + 8 pad elems
#define B_MAT     18432      // 128 * 144
#define B_STAGE   36864      // 2 matrices

// refine scratch (inside SM_B region, used after mainloop)
#define SM_RV1    (SM_B)             // 128*4 f32
#define SM_RV2    (SM_B + 2048)
#define SM_RI1    (SM_B + 4096)
#define SM_XR     (SM_B + 8192)      // 256 f32
#define SM_RPART  (SM_B + 10240)     // 256 f64
#define SM_RFV    (SM_B + 12288)     // 256 f32
#define SM_RFI    (SM_B + 13312)     // 256 int
#define SM_RMISC  (SM_B + 14336)     // sel, vm
#define SM_FLAGS  (SM_B + 15360)     // 128 int
#define SM_FLAGC  (SM_B + 15872)     // 1 int

__device__ float                          g_cnorm[1024];
__device__ __align__(256) __nv_bfloat16   g_ch[1024 * 256];
__device__ __align__(256) __nv_bfloat16   g_cl[1024 * 256];

// ---------------------------------------------------------------------------
__device__ __forceinline__ uint32_t smem_to_u32(const void* p) {
    uint32_t a;
    asm("{ .reg .u64 t; cvta.to.shared.u64 t, %1; cvt.u32.u64 %0, t; }"
        : "=r"(a) : "l"(p));
    return a;
}
__device__ __forceinline__ void cp16(uint32_t dst, const void* src) {
    asm volatile("cp.async.cg.shared.global [%0], [%1], 16;"
                 :: "r"(dst), "l"(src));
}
#define CP_COMMIT() asm volatile("cp.async.commit_group;" ::: "memory")
#define CP_WAIT(n)  asm volatile("cp.async.wait_group %0;" :: "n"(n) : "memory")

__device__ __forceinline__ void ldsm4(uint32_t* r, uint32_t addr) {
    asm volatile("ldmatrix.sync.aligned.m8n8.x4.shared.b16 {%0,%1,%2,%3}, [%4];"
                 : "=r"(r[0]), "=r"(r[1]), "=r"(r[2]), "=r"(r[3]) : "r"(addr));
}
__device__ __forceinline__ void mma_bf16(float* d, const uint32_t* a,
                                         const uint32_t* b) {
    asm volatile(
        "mma.sync.aligned.m16n8k16.row.col.f32.bf16.bf16.f32 "
        "{%0,%1,%2,%3}, {%4,%5,%6,%7}, {%8,%9}, {%0,%1,%2,%3};"
        : "+f"(d[0]), "+f"(d[1]), "+f"(d[2]), "+f"(d[3])
        : "r"(a[0]), "r"(a[1]), "r"(a[2]), "r"(a[3]), "r"(b[0]), "r"(b[1]));
}

// ---------------------------------------------------------------------------
// Merged prep: bf16 hi/lo split + ||c||^2 (fp64 -> fp32). One block per code.
__global__ void prep_codes(const float* __restrict__ codes) {
    __shared__ double partial[256];
    int c = blockIdx.x;
    int t = threadIdx.x;
    float v = codes[(size_t)c * DDIM + t];
    __nv_bfloat16 h = __float2bfloat16_rn(v);
    float lo = v - __bfloat162float(h);
    g_ch[(size_t)c * DDIM + t] = h;
    g_cl[(size_t)c * DDIM + t] = __float2bfloat16_rn(lo);
    partial[t] = (double)v * (double)v;
    __syncthreads();
    for (int s = 128; s; s >>= 1) {
        if (t < s) partial[t] += partial[t + s];
        __syncthreads();
    }
    if (t == 0) g_cnorm[c] = (float)partial[0];
}

// ---------------------------------------------------------------------------
// HMMA ranking kernel (mainloop identical to R12 pass) with FUSED in-block
// refine for ambiguous rows (gap < MARGIN): exact fp64 + tie-window select,
// same formulas as the standalone refine kernel that passed R9-R12.
// ---------------------------------------------------------------------------
__global__ void __launch_bounds__(256, 1)
vq_mma(const float* __restrict__ x, const float* __restrict__ codes,
       float* __restrict__ out, long long out_size, int nrows)
{
    extern __shared__ char smem[];
    const uint32_t sb   = smem_to_u32(smem);
    const int tid  = threadIdx.x;
    const int wid  = tid >> 5;
    const int lane = tid & 31;
    const int wm   = wid & 1;          // m band: rows wm*64
    const int wn   = wid >> 1;         // n band: cols wn*32
    const int row_base = blockIdx.x * BM;

    float* cn_s   = (float*)(smem + SM_CN);
    int*   bidx_s = (int*)(smem + SM_BIDX);

    for (int i = tid; i < CODES; i += 256) cn_s[i] = g_cnorm[i];

    // --- convert x rows to bf16 hi/lo in smem ---
    const float4* x4 = (const float4*)x + (size_t)row_base * (DDIM / 4);
    for (int idx = tid; idx < BM * (DDIM / 4); idx += 256) {
        float4 v = x4[idx];
        int r  = idx >> 6;
        int kq = idx & 63;
        __nv_bfloat16 h0 = __float2bfloat16_rn(v.x);
        __nv_bfloat16 h1 = __float2bfloat16_rn(v.y);
        __nv_bfloat16 h2 = __float2bfloat16_rn(v.z);
        __nv_bfloat16 h3 = __float2bfloat16_rn(v.w);
        __nv_bfloat16 l0 = __float2bfloat16_rn(v.x - __bfloat162float(h0));
        __nv_bfloat16 l1 = __float2bfloat16_rn(v.y - __bfloat162float(h1));
        __nv_bfloat16 l2 = __float2bfloat16_rn(v.z - __bfloat162float(h2));
        __nv_bfloat16 l3 = __float2bfloat16_rn(v.w - __bfloat162float(h3));
        uint32_t h01 = ((uint32_t)__bfloat16_as_ushort(h1) << 16) | __bfloat16_as_ushort(h0);
        uint32_t h23 = ((uint32_t)__bfloat16_as_ushort(h3) << 16) | __bfloat16_as_ushort(h2);
        uint32_t l01 = ((uint32_t)__bfloat16_as_ushort(l1) << 16) | __bfloat16_as_ushort(l0);
        uint32_t l23 = ((uint32_t)__bfloat16_as_ushort(l3) << 16) | __bfloat16_as_ushort(l2);
        int off = r * A_STRIDE + kq * 8;
        *(uint32_t*)(smem + SM_A_H + off)     = h01;
        *(uint32_t*)(smem + SM_A_H + off + 4) = h23;
        *(uint32_t*)(smem + SM_A_L + off)     = l01;
        *(uint32_t*)(smem + SM_A_L + off + 4) = l23;
    }
    __syncthreads();

    float bv[8], b2[8];
    int   bi[8];
    #pragma unroll
    for (int i = 0; i < 8; i++) { bv[i] = 3.4e38f; b2[i] = 3.4e38f; bi[i] = 0; }

    // fragment double buffers
    uint32_t ah[2][4][4], al[2][4][4];
    uint32_t bh[2][2][4], bl[2][2][4];

    for (int chunk = 0; chunk < NCHUNK; chunk++) {
        float acc[4][4][4];
        #pragma unroll
        for (int m = 0; m < 4; m++)
            #pragma unroll
            for (int n = 0; n < 4; n++)
                #pragma unroll
                for (int q = 0; q < 4; q++) acc[m][n][q] = 0.0f;

        {
            #pragma unroll
            for (int i = 0; i < 8; i++) {
                int linear = tid + i * 256;
                int mat = linear >> 10, rr = (linear >> 3) & 127, seg = linear & 7;
                uint32_t dst = sb + SM_B + mat * B_MAT + rr * B_STRIDE + seg * 16;
                const __nv_bfloat16* src = (mat ? g_cl : g_ch)
                    + ((size_t)(chunk * BN + rr) * DDIM + seg * 8);
                cp16(dst, src);
            }
            CP_COMMIT();
        }

        for (int ks = 0; ks < 4; ks++) {
            if (ks < 3) {
                int nb = (ks + 1) & 1;
                #pragma unroll
                for (int i = 0; i < 8; i++) {
                    int linear = tid + i * 256;
                    int mat = linear >> 10, rr = (linear >> 3) & 127, seg = linear & 7;
                    uint32_t dst = sb + SM_B + nb * B_STAGE + mat * B_MAT
                                 + rr * B_STRIDE + seg * 16;
                    const __nv_bfloat16* src = (mat ? g_cl : g_ch)
                        + ((size_t)(chunk * BN + rr) * DDIM + (ks + 1) * 64 + seg * 8);
                    cp16(dst, src);
                }
                CP_COMMIT();
                CP_WAIT(1);
            } else {
                CP_WAIT(0);
            }
            __syncthreads();

            const uint32_t bbase = sb + SM_B + (ks & 1) * B_STAGE;

            #define LDFRAG(BUF, K16) do {                                        \
                int kel_ = (K16) * 16;                                           \
                _Pragma("unroll")                                                \
                for (int mt = 0; mt < 4; mt++) {                                 \
                    uint32_t ar = sb + SM_A_H                                    \
                        + (wm * 64 + mt * 16 + (lane & 15)) * A_STRIDE           \
                        + (ks * 64 + kel_ + (lane >> 4) * 8) * 2;                \
                    ldsm4(ah[BUF][mt], ar);                                      \
                    ldsm4(al[BUF][mt], ar + (SM_A_L - SM_A_H));                  \
                }                                                                \
                _Pragma("unroll")                                                \
                for (int np = 0; np < 2; np++) {                                 \
                    uint32_t br = bbase                                          \
                        + (wn * 32 + np * 16 + (lane & 7) + (lane >> 4) * 8)     \
                          * B_STRIDE                                             \
                        + (kel_ + ((lane >> 3) & 1) * 8) * 2;                    \
                    ldsm4(bh[BUF][np], br);                                      \
                    ldsm4(bl[BUF][np], br + B_MAT);                              \
                }                                                                \
            } while (0)

            LDFRAG(0, 0);
            #pragma unroll
            for (int k16 = 0; k16 < 4; k16++) {
                const int cur = k16 & 1;
                if (k16 < 3) {
                    if (cur == 0) LDFRAG(1, k16 + 1);
                    else          LDFRAG(0, k16 + 1);
                }
                #pragma unroll
                for (int np = 0; np < 2; np++) {
                    #pragma unroll
                    for (int mt = 0; mt < 4; mt++) {
                        mma_bf16(acc[mt][np * 2 + 0], ah[cur][mt], bh[cur][np] + 0);
                        mma_bf16(acc[mt][np * 2 + 1], ah[cur][mt], bh[cur][np] + 2);
                        mma_bf16(acc[mt][np * 2 + 0], ah[cur][mt], bl[cur][np] + 0);
                        mma_bf16(acc[mt][np * 2 + 1], ah[cur][mt], bl[cur][np] + 2);
                        mma_bf16(acc[mt][np * 2 + 0], al[cur][mt], bh[cur][np] + 0);
                        mma_bf16(acc[mt][np * 2 + 1], al[cur][mt], bh[cur][np] + 2);
                    }
                }
            }
            #undef LDFRAG
            __syncthreads();
        }

        // --- chunk epilogue: scores + per-lane top-2 update ---
        #pragma unroll
        for (int mt = 0; mt < 4; mt++) {
            #pragma unroll
            for (int nt = 0; nt < 4; nt++) {
                int col = chunk * BN + wn * 32 + nt * 8 + (lane & 3) * 2;
                float s0 = cn_s[col]     - 2.0f * acc[mt][nt][0];
                float s1 = cn_s[col + 1] - 2.0f * acc[mt][nt][1];
                float s2 = cn_s[col]     - 2.0f * acc[mt][nt][2];
                float s3 = cn_s[col + 1] - 2.0f * acc[mt][nt][3];
                int sl0 = mt * 2, sl1 = mt * 2 + 1;
                if (s0 < bv[sl0]) { b2[sl0] = bv[sl0]; bv[sl0] = s0; bi[sl0] = col; }
                else b2[sl0] = fminf(b2[sl0], s0);
                if (s1 < bv[sl0]) { b2[sl0] = bv[sl0]; bv[sl0] = s1; bi[sl0] = col + 1; }
                else b2[sl0] = fminf(b2[sl0], s1);
                if (s2 < bv[sl1]) { b2[sl1] = bv[sl1]; bv[sl1] = s2; bi[sl1] = col; }
                else b2[sl1] = fminf(b2[sl1], s2);
                if (s3 < bv[sl1]) { b2[sl1] = bv[sl1]; bv[sl1] = s3; bi[sl1] = col + 1; }
                else b2[sl1] = fminf(b2[sl1], s3);
            }
        }
    }

    // --- cross-lane (quad) top-2 merge per row slot ---
    #pragma unroll
    for (int s = 0; s < 8; s++) {
        #pragma unroll
        for (int off = 1; off <= 2; off <<= 1) {
            float ov = __shfl_xor_sync(0xffffffffu, bv[s], off);
            float o2 = __shfl_xor_sync(0xffffffffu, b2[s], off);
            int   oi = __shfl_xor_sync(0xffffffffu, bi[s], off);
            float n2 = fminf(fminf(b2[s], o2), fmaxf(bv[s], ov));
            if (ov < bv[s] || (ov == bv[s] && oi < bi[s])) { bv[s] = ov; bi[s] = oi; }
            b2[s] = n2;
        }
    }
    __syncthreads();   // done with B buffers; reuse as merge scratch

    float* V1 = (float*)(smem + SM_RV1);          // [128][4]
    float* V2 = (float*)(smem + SM_RV2);
    int*   I1 = (int*)(smem + SM_RI1);
    int*   flags   = (int*)(smem + SM_FLAGS);
    int*   flagcnt = (int*)(smem + SM_FLAGC);
    if (tid == 0) *flagcnt = 0;
    if ((lane & 3) == 0) {
        #pragma unroll
        for (int s = 0; s < 8; s++) {
            int mt = s >> 1, hi = s & 1;
            int r = wm * 64 + mt * 16 + (lane >> 2) + hi * 8;
            V1[r * 4 + wn] = bv[s];
            V2[r * 4 + wn] = b2[s];
            I1[r * 4 + wn] = bi[s];
        }
    }
    __syncthreads();

    const long long NQ = (long long)nrows * DDIM;
    if (tid < BM) {
        float v1 = V1[tid * 4], v2 = V2[tid * 4];
        int   i1 = I1[tid * 4];
        #pragma unroll
        for (int j = 1; j < 4; j++) {
            float a1 = V1[tid * 4 + j], a2 = V2[tid * 4 + j];
            int   ai = I1[tid * 4 + j];
            float n2 = fminf(fminf(v2, a2), fmaxf(v1, a1));
            if (a1 < v1 || (a1 == v1 && ai < i1)) { v1 = a1; i1 = ai; }
            v2 = n2;
        }
        bidx_s[tid] = i1;
        long long row = row_base + tid;
        if (v2 - v1 < MARGIN) {
            int slot = atomicAdd(flagcnt, 1);
            flags[slot] = tid;
        }
        if (out_size >= NQ + nrows) out[NQ + row] = (float)i1;
        else if (out_size < NQ && row < out_size) out[row] = (float)i1;
    }
    __syncthreads();

    // --- gather quantized = codes[best] ---
    if (out_size >= NQ) {
        const float4* c4 = (const float4*)codes;
        float4* o4 = (float4*)out;
        for (int i = tid; i < BM * (DDIM / 4); i += 256) {
            int r = i >> 6;
            int q = i & 63;
            o4[(size_t)(row_base + r) * (DDIM / 4) + q] =
                c4[(size_t)bidx_s[r] * (DDIM / 4) + q];
        }
    }
    __syncthreads();

    // =======================================================================
    // Fused refine: exact re-decision for flagged rows (formulas identical
    // to the standalone refine kernel that passed R9-R12).
    // =======================================================================
    const int nflag = *flagcnt;
    if (nflag == 0) return;

    float*  xr      = (float*)(smem + SM_XR);
    double* rpart   = (double*)(smem + SM_RPART);
    float*  rfv     = (float*)(smem + SM_RFV);
    int*    rfi     = (int*)(smem + SM_RFI);
    int*    sel_s   = (int*)(smem + SM_RMISC);
    float*  vm_s    = (float*)(smem + SM_RMISC + 8);

    for (int f = 0; f < nflag; f++) {
        const int  lrow = flags[f];
        const long long row = row_base + lrow;

        xr[tid] = x[(size_t)row * DDIM + tid];
        __syncthreads();

        // s1 = ||x||^2 correctly rounded
        rpart[tid] = (double)xr[tid] * (double)xr[tid];
        __syncthreads();
        for (int s = 128; s; s >>= 1) {
            if (tid < s) rpart[tid] += rpart[tid + s];
            __syncthreads();
        }
        float s1f = (float)rpart[0];

        // pass 1: fp32 scores via float4, 16 interleaved chains
        const float4* xr4 = (const float4*)xr;
        const float4* crow4[4];
        #pragma unroll
        for (int g = 0; g < 4; g++)
            crow4[g] = (const float4*)(codes + (size_t)(tid + 256 * g) * DDIM);

        float4 accv[4];
        #pragma unroll
        for (int g = 0; g < 4; g++) accv[g] = make_float4(0.f, 0.f, 0.f, 0.f);

        #pragma unroll 4
        for (int k4 = 0; k4 < DDIM / 4; k4++) {
            float4 xv = xr4[k4];
            #pragma unroll
            for (int g = 0; g < 4; g++) {
                float4 cv = __ldg(&crow4[g][k4]);
                accv[g].x = fmaf(xv.x, cv.x, accv[g].x);
                accv[g].y = fmaf(xv.y, cv.y, accv[g].y);
                accv[g].z = fmaf(xv.z, cv.z, accv[g].z);
                accv[g].w = fmaf(xv.w, cv.w, accv[g].w);
            }
        }

        float dv[4];
        #pragma unroll
        for (int g = 0; g < 4; g++) {
            float dot = (accv[g].x + accv[g].y) + (accv[g].z + accv[g].w);
            dv[g] = (s1f - 2.0f * dot) + cn_s[tid + 256 * g];
        }

        float bvv = fminf(fminf(dv[0], dv[1]), fminf(dv[2], dv[3]));
        rfv[tid] = bvv;
        __syncthreads();
        for (int s = 128; s; s >>= 1) {
            if (tid < s) rfv[tid] = fminf(rfv[tid], rfv[tid + s]);
            __syncthreads();
        }
        float filt = rfv[0] + FILT_EPS;
        __syncthreads();

        // pass 2: fp64 (4 interleaved chains) -> d32 for survivors
        float ev[4];
        #pragma unroll
        for (int g = 0; g < 4; g++) {
            int c = tid + 256 * g;
            ev[g] = 3.4e38f;
            if (dv[g] <= filt) {
                const float* crow = codes + (size_t)c * DDIM;
                double d0 = 0.0, d1 = 0.0, d2 = 0.0, d3 = 0.0;
                #pragma unroll 4
                for (int k = 0; k < DDIM; k += 4) {
                    d0 = fma((double)xr[k],     (double)__ldg(&crow[k]),     d0);
                    d1 = fma((double)xr[k + 1], (double)__ldg(&crow[k + 1]), d1);
                    d2 = fma((double)xr[k + 2], (double)__ldg(&crow[k + 2]), d2);
                    d3 = fma((double)xr[k + 3], (double)__ldg(&crow[k + 3]), d3);
                }
                double dot = (d0 + d1) + (d2 + d3);
                float dotf = (float)dot;
                float t1   = s1f - 2.0f * dotf;
                ev[g]      = t1 + cn_s[c];
            }
        }

        float bvx = fminf(fminf(ev[0], ev[1]), fminf(ev[2], ev[3]));
        rfv[tid] = bvx;
        __syncthreads();
        for (int s = 128; s; s >>= 1) {
            if (tid < s) rfv[tid] = fminf(rfv[tid], rfv[tid + s]);
            __syncthreads();
        }
        if (tid == 0) *vm_s = rfv[0];
        __syncthreads();
        float vm = *vm_s;
        float tie_hi = __int_as_float(__float_as_int(vm) + TIE_ULPS);

        int bii = 0x7fffffff;
        #pragma unroll
        for (int g = 0; g < 4; g++) {
            int c = tid + 256 * g;
            if (ev[g] <= tie_hi && c < bii) bii = c;
        }
        rfi[tid] = bii;
        __syncthreads();
        for (int s = 128; s; s >>= 1) {
            if (tid < s) rfi[tid] = min(rfi[tid], rfi[tid + s]);
            __syncthreads();
        }
        if (tid == 0) {
            *sel_s = rfi[0];
            if (out_size >= NQ + nrows) out[NQ + row] = (float)rfi[0];
            else if (out_size < NQ && row < out_size) out[row] = (float)rfi[0];
        }
        __syncthreads();

        if (out_size >= NQ)
            out[(size_t)row * DDIM + tid] = codes[(size_t)(*sel_s) * DDIM + tid];
        __syncthreads();
    }
}

// ---------------------------------------------------------------------------
extern "C" void kernel_launch(void* const* d_in, const int* in_sizes, int n_in,
                              void* d_out, int out_size)
{
    const float* x     = (const float*)d_in[0];
    const float* codes = (const float*)d_in[1];
    int nrows = in_sizes[0] / DDIM;   // 65536
    int C     = in_sizes[1] / DDIM;   // 1024

    cudaFuncSetAttribute(vq_mma, cudaFuncAttributeMaxDynamicSharedMemorySize,
                         SM_TOTAL);

    prep_codes<<<C, 256>>>(codes);

    vq_mma<<<nrows / BM, 256, SM_TOTAL>>>(x, codes, (float*)d_out,
                                          (long long)out_size, nrows);
}

// round 14
// speedup vs baseline: 1.0746x; 1.0746x over previous
#include <cuda_runtime.h>
#include <cuda_bf16.h>
#include <cstdint>

// Problem constants (fixed by dataset)
#define DDIM 256
#define CODES 1024
#define BM   128          // rows per CTA
#define BN   128          // codes per chunk
#define NCHUNK 8
#define MARGIN 2e-3f
#define TIE_ULPS 2
#define FILT_EPS 4e-3f

// dynamic smem layout (bytes)
#define SM_CN     0          // 1024 f32          (4096)
#define SM_BIDX   4096       // 128 int           (512)
#define SM_A_H    8192       // 128 rows x 528B   (67584)
#define SM_A_L    75776      // 128 rows x 528B   (67584)
#define SM_B      143360     // 2 stages x 2 mats x 128 x 144B (73728)
#define SM_TOTAL  217088
#define A_STRIDE  528        // 256 bf16 + 8 pad elems
#define B_STRIDE  144        // 64 bf16 + 8 pad elems
#define B_MAT     18432      // 128 * 144
#define B_STAGE   36864      // 2 matrices

__device__ float                          g_cnorm[1024];
__device__ __align__(256) __nv_bfloat16   g_ch[1024 * 256];
__device__ __align__(256) __nv_bfloat16   g_cl[1024 * 256];
__device__ int                            g_list[65536];
__device__ int                            g_cnt;

// ---------------------------------------------------------------------------
__device__ __forceinline__ uint32_t smem_to_u32(const void* p) {
    uint32_t a;
    asm("{ .reg .u64 t; cvta.to.shared.u64 t, %1; cvt.u32.u64 %0, t; }"
        : "=r"(a) : "l"(p));
    return a;
}
__device__ __forceinline__ void cp16(uint32_t dst, const void* src) {
    asm volatile("cp.async.cg.shared.global [%0], [%1], 16;"
                 :: "r"(dst), "l"(src));
}
#define CP_COMMIT() asm volatile("cp.async.commit_group;" ::: "memory")
#define CP_WAIT(n)  asm volatile("cp.async.wait_group %0;" :: "n"(n) : "memory")

__device__ __forceinline__ void ldsm4(uint32_t* r, uint32_t addr) {
    asm volatile("ldmatrix.sync.aligned.m8n8.x4.shared.b16 {%0,%1,%2,%3}, [%4];"
                 : "=r"(r[0]), "=r"(r[1]), "=r"(r[2]), "=r"(r[3]) : "r"(addr));
}
__device__ __forceinline__ void mma_bf16(float* d, const uint32_t* a,
                                         const uint32_t* b) {
    asm volatile(
        "mma.sync.aligned.m16n8k16.row.col.f32.bf16.bf16.f32 "
        "{%0,%1,%2,%3}, {%4,%5,%6,%7}, {%8,%9}, {%0,%1,%2,%3};"
        : "+f"(d[0]), "+f"(d[1]), "+f"(d[2]), "+f"(d[3])
        : "r"(a[0]), "r"(a[1]), "r"(a[2]), "r"(a[3]), "r"(b[0]), "r"(b[1]));
}

// ---------------------------------------------------------------------------
// Merged prep: bf16 hi/lo split + ||c||^2 (fp64 -> fp32) + g_cnt reset.
__global__ void prep_codes(const float* __restrict__ codes) {
    __shared__ double partial[256];
    int c = blockIdx.x;
    int t = threadIdx.x;
    if (c == 0 && t == 0) g_cnt = 0;
    float v = codes[(size_t)c * DDIM + t];
    __nv_bfloat16 h = __float2bfloat16_rn(v);
    float lo = v - __bfloat162float(h);
    g_ch[(size_t)c * DDIM + t] = h;
    g_cl[(size_t)c * DDIM + t] = __float2bfloat16_rn(lo);
    partial[t] = (double)v * (double)v;
    __syncthreads();
    for (int s = 128; s; s >>= 1) {
        if (t < s) partial[t] += partial[t + s];
        __syncthreads();
    }
    if (t == 0) g_cnorm[c] = (float)partial[0];
}

// ---------------------------------------------------------------------------
// HMMA ranking kernel (identical to the R12 passing version; MARGIN 2e-3).
// dot = xh.ch + xh.cl + xl.ch (bf16 in, fp32 acc)
// ---------------------------------------------------------------------------
__global__ void __launch_bounds__(256, 1)
vq_mma(const float* __restrict__ x, const float* __restrict__ codes,
       float* __restrict__ out, long long out_size, int nrows)
{
    extern __shared__ char smem[];
    const uint32_t sb   = smem_to_u32(smem);
    const int tid  = threadIdx.x;
    const int wid  = tid >> 5;
    const int lane = tid & 31;
    const int wm   = wid & 1;          // m band: rows wm*64
    const int wn   = wid >> 1;         // n band: cols wn*32
    const int row_base = blockIdx.x * BM;

    float* cn_s   = (float*)(smem + SM_CN);
    int*   bidx_s = (int*)(smem + SM_BIDX);

    for (int i = tid; i < CODES; i += 256) cn_s[i] = g_cnorm[i];

    const float4* x4 = (const float4*)x + (size_t)row_base * (DDIM / 4);
    for (int idx = tid; idx < BM * (DDIM / 4); idx += 256) {
        float4 v = x4[idx];
        int r  = idx >> 6;
        int kq = idx & 63;
        __nv_bfloat16 h0 = __float2bfloat16_rn(v.x);
        __nv_bfloat16 h1 = __float2bfloat16_rn(v.y);
        __nv_bfloat16 h2 = __float2bfloat16_rn(v.z);
        __nv_bfloat16 h3 = __float2bfloat16_rn(v.w);
        __nv_bfloat16 l0 = __float2bfloat16_rn(v.x - __bfloat162float(h0));
        __nv_bfloat16 l1 = __float2bfloat16_rn(v.y - __bfloat162float(h1));
        __nv_bfloat16 l2 = __float2bfloat16_rn(v.z - __bfloat162float(h2));
        __nv_bfloat16 l3 = __float2bfloat16_rn(v.w - __bfloat162float(h3));
        uint32_t h01 = ((uint32_t)__bfloat16_as_ushort(h1) << 16) | __bfloat16_as_ushort(h0);
        uint32_t h23 = ((uint32_t)__bfloat16_as_ushort(h3) << 16) | __bfloat16_as_ushort(h2);
        uint32_t l01 = ((uint32_t)__bfloat16_as_ushort(l1) << 16) | __bfloat16_as_ushort(l0);
        uint32_t l23 = ((uint32_t)__bfloat16_as_ushort(l3) << 16) | __bfloat16_as_ushort(l2);
        int off = r * A_STRIDE + kq * 8;
        *(uint32_t*)(smem + SM_A_H + off)     = h01;
        *(uint32_t*)(smem + SM_A_H + off + 4) = h23;
        *(uint32_t*)(smem + SM_A_L + off)     = l01;
        *(uint32_t*)(smem + SM_A_L + off + 4) = l23;
    }
    __syncthreads();

    float bv[8], b2[8];
    int   bi[8];
    #pragma unroll
    for (int i = 0; i < 8; i++) { bv[i] = 3.4e38f; b2[i] = 3.4e38f; bi[i] = 0; }

    uint32_t ah[2][4][4], al[2][4][4];
    uint32_t bh[2][2][4], bl[2][2][4];

    for (int chunk = 0; chunk < NCHUNK; chunk++) {
        float acc[4][4][4];
        #pragma unroll
        for (int m = 0; m < 4; m++)
            #pragma unroll
            for (int n = 0; n < 4; n++)
                #pragma unroll
                for (int q = 0; q < 4; q++) acc[m][n][q] = 0.0f;

        {
            #pragma unroll
            for (int i = 0; i < 8; i++) {
                int linear = tid + i * 256;
                int mat = linear >> 10, rr = (linear >> 3) & 127, seg = linear & 7;
                uint32_t dst = sb + SM_B + mat * B_MAT + rr * B_STRIDE + seg * 16;
                const __nv_bfloat16* src = (mat ? g_cl : g_ch)
                    + ((size_t)(chunk * BN + rr) * DDIM + seg * 8);
                cp16(dst, src);
            }
            CP_COMMIT();
        }

        for (int ks = 0; ks < 4; ks++) {
            if (ks < 3) {
                int nb = (ks + 1) & 1;
                #pragma unroll
                for (int i = 0; i < 8; i++) {
                    int linear = tid + i * 256;
                    int mat = linear >> 10, rr = (linear >> 3) & 127, seg = linear & 7;
                    uint32_t dst = sb + SM_B + nb * B_STAGE + mat * B_MAT
                                 + rr * B_STRIDE + seg * 16;
                    const __nv_bfloat16* src = (mat ? g_cl : g_ch)
                        + ((size_t)(chunk * BN + rr) * DDIM + (ks + 1) * 64 + seg * 8);
                    cp16(dst, src);
                }
                CP_COMMIT();
                CP_WAIT(1);
            } else {
                CP_WAIT(0);
            }
            __syncthreads();

            const uint32_t bbase = sb + SM_B + (ks & 1) * B_STAGE;

            #define LDFRAG(BUF, K16) do {                                        \
                int kel_ = (K16) * 16;                                           \
                _Pragma("unroll")                                                \
                for (int mt = 0; mt < 4; mt++) {                                 \
                    uint32_t ar = sb + SM_A_H                                    \
                        + (wm * 64 + mt * 16 + (lane & 15)) * A_STRIDE           \
                        + (ks * 64 + kel_ + (lane >> 4) * 8) * 2;                \
                    ldsm4(ah[BUF][mt], ar);                                      \
                    ldsm4(al[BUF][mt], ar + (SM_A_L - SM_A_H));                  \
                }                                                                \
                _Pragma("unroll")                                                \
                for (int np = 0; np < 2; np++) {                                 \
                    uint32_t br = bbase                                          \
                        + (wn * 32 + np * 16 + (lane & 7) + (lane >> 4) * 8)     \
                          * B_STRIDE                                             \
                        + (kel_ + ((lane >> 3) & 1) * 8) * 2;                    \
                    ldsm4(bh[BUF][np], br);                                      \
                    ldsm4(bl[BUF][np], br + B_MAT);                              \
                }                                                                \
            } while (0)

            LDFRAG(0, 0);
            #pragma unroll
            for (int k16 = 0; k16 < 4; k16++) {
                const int cur = k16 & 1;
                if (k16 < 3) {
                    if (cur == 0) LDFRAG(1, k16 + 1);
                    else          LDFRAG(0, k16 + 1);
                }
                #pragma unroll
                for (int np = 0; np < 2; np++) {
                    #pragma unroll
                    for (int mt = 0; mt < 4; mt++) {
                        mma_bf16(acc[mt][np * 2 + 0], ah[cur][mt], bh[cur][np] + 0);
                        mma_bf16(acc[mt][np * 2 + 1], ah[cur][mt], bh[cur][np] + 2);
                        mma_bf16(acc[mt][np * 2 + 0], ah[cur][mt], bl[cur][np] + 0);
                        mma_bf16(acc[mt][np * 2 + 1], ah[cur][mt], bl[cur][np] + 2);
                        mma_bf16(acc[mt][np * 2 + 0], al[cur][mt], bh[cur][np] + 0);
                        mma_bf16(acc[mt][np * 2 + 1], al[cur][mt], bh[cur][np] + 2);
                    }
                }
            }
            #undef LDFRAG
            __syncthreads();
        }

        #pragma unroll
        for (int mt = 0; mt < 4; mt++) {
            #pragma unroll
            for (int nt = 0; nt < 4; nt++) {
                int col = chunk * BN + wn * 32 + nt * 8 + (lane & 3) * 2;
                float s0 = cn_s[col]     - 2.0f * acc[mt][nt][0];
                float s1 = cn_s[col + 1] - 2.0f * acc[mt][nt][1];
                float s2 = cn_s[col]     - 2.0f * acc[mt][nt][2];
                float s3 = cn_s[col + 1] - 2.0f * acc[mt][nt][3];
                int sl0 = mt * 2, sl1 = mt * 2 + 1;
                if (s0 < bv[sl0]) { b2[sl0] = bv[sl0]; bv[sl0] = s0; bi[sl0] = col; }
                else b2[sl0] = fminf(b2[sl0], s0);
                if (s1 < bv[sl0]) { b2[sl0] = bv[sl0]; bv[sl0] = s1; bi[sl0] = col + 1; }
                else b2[sl0] = fminf(b2[sl0], s1);
                if (s2 < bv[sl1]) { b2[sl1] = bv[sl1]; bv[sl1] = s2; bi[sl1] = col; }
                else b2[sl1] = fminf(b2[sl1], s2);
                if (s3 < bv[sl1]) { b2[sl1] = bv[sl1]; bv[sl1] = s3; bi[sl1] = col + 1; }
                else b2[sl1] = fminf(b2[sl1], s3);
            }
        }
    }

    #pragma unroll
    for (int s = 0; s < 8; s++) {
        #pragma unroll
        for (int off = 1; off <= 2; off <<= 1) {
            float ov = __shfl_xor_sync(0xffffffffu, bv[s], off);
            float o2 = __shfl_xor_sync(0xffffffffu, b2[s], off);
            int   oi = __shfl_xor_sync(0xffffffffu, bi[s], off);
            float n2 = fminf(fminf(b2[s], o2), fmaxf(bv[s], ov));
            if (ov < bv[s] || (ov == bv[s] && oi < bi[s])) { bv[s] = ov; bi[s] = oi; }
            b2[s] = n2;
        }
    }
    __syncthreads();

    float* V1 = (float*)(smem + SM_B);
    float* V2 = (float*)(smem + SM_B + 2048);
    int*   I1 = (int*)(smem + SM_B + 4096);
    if ((lane & 3) == 0) {
        #pragma unroll
        for (int s = 0; s < 8; s++) {
            int mt = s >> 1, hi = s & 1;
            int r = wm * 64 + mt * 16 + (lane >> 2) + hi * 8;
            V1[r * 4 + wn] = bv[s];
            V2[r * 4 + wn] = b2[s];
            I1[r * 4 + wn] = bi[s];
        }
    }
    __syncthreads();

    const long long NQ = (long long)nrows * DDIM;
    if (tid < BM) {
        float v1 = V1[tid * 4], v2 = V2[tid * 4];
        int   i1 = I1[tid * 4];
        #pragma unroll
        for (int j = 1; j < 4; j++) {
            float a1 = V1[tid * 4 + j], a2 = V2[tid * 4 + j];
            int   ai = I1[tid * 4 + j];
            float n2 = fminf(fminf(v2, a2), fmaxf(v1, a1));
            if (a1 < v1 || (a1 == v1 && ai < i1)) { v1 = a1; i1 = ai; }
            v2 = n2;
        }
        bidx_s[tid] = i1;
        long long row = row_base + tid;
        if (v2 - v1 < MARGIN) {
            int slot = atomicAdd(&g_cnt, 1);
            g_list[slot] = (int)row;
        }
        if (out_size >= NQ + nrows) out[NQ + row] = (float)i1;
        else if (out_size < NQ && row < out_size) out[row] = (float)i1;
    }
    __syncthreads();

    if (out_size >= NQ) {
        const float4* c4 = (const float4*)codes;
        float4* o4 = (float4*)out;
        for (int i = tid; i < BM * (DDIM / 4); i += 256) {
            int r = i >> 6;
            int q = i & 63;
            o4[(size_t)(row_base + r) * (DDIM / 4) + q] =
                c4[(size_t)bidx_s[r] * (DDIM / 4) + q];
        }
    }
}

// ---------------------------------------------------------------------------
// Refine kernel v6: 1024 threads, ONE code per thread (no spill possible),
// unroll-8 float4 loads for high MLP. Decision formulas identical to the
// R9-R13 passing versions: fp32 prefilter + FILT_EPS, fp64 exact pass,
// tie-window (TIE_ULPS) lowest-index select.
// ---------------------------------------------------------------------------
__global__ void __launch_bounds__(1024)
refine_kernel(const float* __restrict__ x, const float* __restrict__ codes,
              float* __restrict__ out, long long NQ, long long out_size,
              int nrows, int C)
{
    __shared__ __align__(16) float xr[DDIM];
    __shared__ double partial[256];
    __shared__ float  fv[1024];
    __shared__ int    fi[1024];
    __shared__ int    sel;
    __shared__ float  vm_s, filt_s;

    const int t = threadIdx.x;
    int cnt = g_cnt;
    if (cnt > 65536) cnt = 65536;

    for (int w = blockIdx.x; w < cnt; w += gridDim.x) {
        int row = g_list[w];
        if (t < DDIM) xr[t] = x[(size_t)row * DDIM + t];
        __syncthreads();

        // s1 = ||x||^2 correctly rounded (fp64 tree)
        if (t < 256) partial[t] = (double)xr[t] * (double)xr[t];
        __syncthreads();
        for (int s = 128; s; s >>= 1) {
            if (t < s) partial[t] += partial[t + s];
            __syncthreads();
        }
        float s1f = (float)partial[0];

        // --- pass 1: fp32 score for MY code (4 chains, ~10 live regs) ---
        const int c = t;
        const float4* crow = (const float4*)(codes + (size_t)c * DDIM);
        const float4* xr4  = (const float4*)xr;
        float a0 = 0.f, a1 = 0.f, a2 = 0.f, a3 = 0.f;
        #pragma unroll 8
        for (int k4 = 0; k4 < DDIM / 4; k4++) {
            float4 cv = __ldg(&crow[k4]);
            float4 xv = xr4[k4];
            a0 = fmaf(cv.x, xv.x, a0);
            a1 = fmaf(cv.y, xv.y, a1);
            a2 = fmaf(cv.z, xv.z, a2);
            a3 = fmaf(cv.w, xv.w, a3);
        }
        float dot = (a0 + a1) + (a2 + a3);
        float dv  = (s1f - 2.0f * dot) + g_cnorm[c];

        // block min of fp32 scores
        fv[t] = dv;
        __syncthreads();
        for (int s = 512; s; s >>= 1) {
            if (t < s) fv[t] = fminf(fv[t], fv[t + s]);
            __syncthreads();
        }
        if (t == 0) filt_s = fv[0] + FILT_EPS;
        __syncthreads();
        float filt = filt_s;

        // --- pass 2: exact fp64 -> d32 for survivors only ---
        float ev = 3.4e38f;
        if (dv <= filt) {
            const float* cr = codes + (size_t)c * DDIM;
            double d0 = 0.0, d1 = 0.0, d2 = 0.0, d3 = 0.0;
            #pragma unroll 4
            for (int k = 0; k < DDIM; k += 4) {
                d0 = fma((double)xr[k],     (double)__ldg(&cr[k]),     d0);
                d1 = fma((double)xr[k + 1], (double)__ldg(&cr[k + 1]), d1);
                d2 = fma((double)xr[k + 2], (double)__ldg(&cr[k + 2]), d2);
                d3 = fma((double)xr[k + 3], (double)__ldg(&cr[k + 3]), d3);
            }
            double dd = (d0 + d1) + (d2 + d3);
            float dotf = (float)dd;
            float t1   = s1f - 2.0f * dotf;
            ev = t1 + g_cnorm[c];
        }

        fv[t] = ev;
        __syncthreads();
        for (int s = 512; s; s >>= 1) {
            if (t < s) fv[t] = fminf(fv[t], fv[t + s]);
            __syncthreads();
        }
        if (t == 0) vm_s = fv[0];
        __syncthreads();
        float vm = vm_s;
        float tie_hi = __int_as_float(__float_as_int(vm) + TIE_ULPS);

        fi[t] = (ev <= tie_hi) ? c : 0x7fffffff;
        __syncthreads();
        for (int s = 512; s; s >>= 1) {
            if (t < s) fi[t] = min(fi[t], fi[t + s]);
            __syncthreads();
        }
        if (t == 0) {
            sel = fi[0];
            if (out_size >= NQ + nrows) out[NQ + row] = (float)fi[0];
            else if (out_size < NQ && row < out_size) out[row] = (float)fi[0];
        }
        __syncthreads();

        if (out_size >= NQ && t < DDIM)
            out[(size_t)row * DDIM + t] = codes[(size_t)sel * DDIM + t];
        __syncthreads();
    }
}

// ---------------------------------------------------------------------------
extern "C" void kernel_launch(void* const* d_in, const int* in_sizes, int n_in,
                              void* d_out, int out_size)
{
    const float* x     = (const float*)d_in[0];
    const float* codes = (const float*)d_in[1];
    int nrows = in_sizes[0] / DDIM;   // 65536
    int C     = in_sizes[1] / DDIM;   // 1024

    cudaFuncSetAttribute(vq_mma, cudaFuncAttributeMaxDynamicSharedMemorySize,
                         SM_TOTAL);

    prep_codes<<<C, 256>>>(codes);

    vq_mma<<<nrows / BM, 256, SM_TOTAL>>>(x, codes, (float*)d_out,
                                          (long long)out_size, nrows);

    long long NQ = (long long)nrows * DDIM;
    refine_kernel<<<1024, 1024>>>(x, codes, (float*)d_out, NQ,
                                  (long long)out_size, nrows, C);
}

// round 15
// speedup vs baseline: 1.1402x; 1.0611x over previous
#include <cuda_runtime.h>
#include <cuda_bf16.h>
#include <cstdint>

// Problem constants (fixed by dataset)
#define DDIM 256
#define CODES 1024
#define BM   64           // rows per CTA (2 CTAs/SM)
#define BN   128          // codes per chunk
#define NCHUNK 8
#define MARGIN 2e-3f
#define TIE_ULPS 2
#define FILT_EPS 4e-3f

// dynamic smem layout (bytes) — total 112640 => 2 CTAs/SM (225KB < 228KB)
#define SM_CN     0          // 1024 f32 (4096)
#define SM_BIDX   4096       // 64 int (256)
#define SM_A_H    8192       // 64 rows x 528B (33792)
#define SM_A_L    41984      // 64 rows x 528B (33792)
#define SM_B      75776      // 1 stage x 2 mats x 128 x 144B (36864)
#define SM_TOTAL  112640
#define A_STRIDE  528        // bytes per A row (256 bf16 + pad)
#define B_STRIDE  144        // bytes per B row (64 bf16 + pad)
#define B_MAT     18432      // 128 * 144

__device__ float                          g_cnorm[1024];
__device__ __align__(256) __nv_bfloat16   g_ch[1024 * 256];
__device__ __align__(256) __nv_bfloat16   g_cl[1024 * 256];
__device__ int                            g_list[65536];
__device__ int                            g_cnt;

// ---------------------------------------------------------------------------
__device__ __forceinline__ uint32_t smem_to_u32(const void* p) {
    uint32_t a;
    asm("{ .reg .u64 t; cvta.to.shared.u64 t, %1; cvt.u32.u64 %0, t; }"
        : "=r"(a) : "l"(p));
    return a;
}
__device__ __forceinline__ void cp16(uint32_t dst, const void* src) {
    asm volatile("cp.async.cg.shared.global [%0], [%1], 16;"
                 :: "r"(dst), "l"(src));
}
#define CP_COMMIT() asm volatile("cp.async.commit_group;" ::: "memory")
#define CP_WAIT(n)  asm volatile("cp.async.wait_group %0;" :: "n"(n) : "memory")

__device__ __forceinline__ void ldsm4(uint32_t* r, uint32_t addr) {
    asm volatile("ldmatrix.sync.aligned.m8n8.x4.shared.b16 {%0,%1,%2,%3}, [%4];"
                 : "=r"(r[0]), "=r"(r[1]), "=r"(r[2]), "=r"(r[3]) : "r"(addr));
}
__device__ __forceinline__ void mma_bf16(float* d, const uint32_t* a,
                                         const uint32_t* b) {
    asm volatile(
        "mma.sync.aligned.m16n8k16.row.col.f32.bf16.bf16.f32 "
        "{%0,%1,%2,%3}, {%4,%5,%6,%7}, {%8,%9}, {%0,%1,%2,%3};"
        : "+f"(d[0]), "+f"(d[1]), "+f"(d[2]), "+f"(d[3])
        : "r"(a[0]), "r"(a[1]), "r"(a[2]), "r"(a[3]), "r"(b[0]), "r"(b[1]));
}

// ---------------------------------------------------------------------------
// Merged prep: bf16 hi/lo split + ||c||^2 (fp64 -> fp32) + g_cnt reset.
__global__ void prep_codes(const float* __restrict__ codes) {
    __shared__ double partial[256];
    int c = blockIdx.x;
    int t = threadIdx.x;
    if (c == 0 && t == 0) g_cnt = 0;
    float v = codes[(size_t)c * DDIM + t];
    __nv_bfloat16 h = __float2bfloat16_rn(v);
    float lo = v - __bfloat162float(h);
    g_ch[(size_t)c * DDIM + t] = h;
    g_cl[(size_t)c * DDIM + t] = __float2bfloat16_rn(lo);
    partial[t] = (double)v * (double)v;
    __syncthreads();
    for (int s = 128; s; s >>= 1) {
        if (t < s) partial[t] += partial[t + s];
        __syncthreads();
    }
    if (t == 0) g_cnorm[c] = (float)partial[0];
}

// ---------------------------------------------------------------------------
// HMMA ranking kernel: BM=64 per CTA, 256 threads / 8 warps (2m x 4n bands,
// warp tile 32x32), single-stage B, 2 CTAs/SM for cross-CTA LDSM/HMMA overlap.
// dot = xh.ch + xh.cl + xl.ch (bf16 in, fp32 acc)
// ---------------------------------------------------------------------------
__global__ void __launch_bounds__(256, 2)
vq_mma(const float* __restrict__ x, const float* __restrict__ codes,
       float* __restrict__ out, long long out_size, int nrows)
{
    extern __shared__ char smem[];
    const uint32_t sb   = smem_to_u32(smem);
    const int tid  = threadIdx.x;
    const int wid  = tid >> 5;
    const int lane = tid & 31;
    const int wm   = wid & 1;          // m band: rows wm*32
    const int wn   = wid >> 1;         // n band: cols wn*32
    const int row_base = blockIdx.x * BM;

    float* cn_s   = (float*)(smem + SM_CN);
    int*   bidx_s = (int*)(smem + SM_BIDX);

    for (int i = tid; i < CODES; i += 256) cn_s[i] = g_cnorm[i];

    // --- convert x rows to bf16 hi/lo in smem ---
    const float4* x4 = (const float4*)x + (size_t)row_base * (DDIM / 4);
    for (int idx = tid; idx < BM * (DDIM / 4); idx += 256) {
        float4 v = x4[idx];
        int r  = idx >> 6;
        int kq = idx & 63;
        __nv_bfloat16 h0 = __float2bfloat16_rn(v.x);
        __nv_bfloat16 h1 = __float2bfloat16_rn(v.y);
        __nv_bfloat16 h2 = __float2bfloat16_rn(v.z);
        __nv_bfloat16 h3 = __float2bfloat16_rn(v.w);
        __nv_bfloat16 l0 = __float2bfloat16_rn(v.x - __bfloat162float(h0));
        __nv_bfloat16 l1 = __float2bfloat16_rn(v.y - __bfloat162float(h1));
        __nv_bfloat16 l2 = __float2bfloat16_rn(v.z - __bfloat162float(h2));
        __nv_bfloat16 l3 = __float2bfloat16_rn(v.w - __bfloat162float(h3));
        uint32_t h01 = ((uint32_t)__bfloat16_as_ushort(h1) << 16) | __bfloat16_as_ushort(h0);
        uint32_t h23 = ((uint32_t)__bfloat16_as_ushort(h3) << 16) | __bfloat16_as_ushort(h2);
        uint32_t l01 = ((uint32_t)__bfloat16_as_ushort(l1) << 16) | __bfloat16_as_ushort(l0);
        uint32_t l23 = ((uint32_t)__bfloat16_as_ushort(l3) << 16) | __bfloat16_as_ushort(l2);
        int off = r * A_STRIDE + kq * 8;
        *(uint32_t*)(smem + SM_A_H + off)     = h01;
        *(uint32_t*)(smem + SM_A_H + off + 4) = h23;
        *(uint32_t*)(smem + SM_A_L + off)     = l01;
        *(uint32_t*)(smem + SM_A_L + off + 4) = l23;
    }
    __syncthreads();

    // per-lane top-2: 4 row slots (mt*2 + hi)
    float bv[4], b2[4];
    int   bi[4];
    #pragma unroll
    for (int i = 0; i < 4; i++) { bv[i] = 3.4e38f; b2[i] = 3.4e38f; bi[i] = 0; }

    for (int chunk = 0; chunk < NCHUNK; chunk++) {
        float acc[2][4][4];
        #pragma unroll
        for (int m = 0; m < 2; m++)
            #pragma unroll
            for (int n = 0; n < 4; n++)
                #pragma unroll
                for (int q = 0; q < 4; q++) acc[m][n][q] = 0.0f;

        for (int ks = 0; ks < 4; ks++) {
            __syncthreads();   // previous ks reads done before overwrite
            // load B tile for this ks: 2 mats x 128 rows x 8 segs = 2048 segs
            #pragma unroll
            for (int i = 0; i < 8; i++) {
                int linear = tid + i * 256;
                int mat = linear >> 10, rr = (linear >> 3) & 127, seg = linear & 7;
                uint32_t dst = sb + SM_B + mat * B_MAT + rr * B_STRIDE + seg * 16;
                const __nv_bfloat16* src = (mat ? g_cl : g_ch)
                    + ((size_t)(chunk * BN + rr) * DDIM + ks * 64 + seg * 8);
                cp16(dst, src);
            }
            CP_COMMIT();
            CP_WAIT(0);
            __syncthreads();

            #pragma unroll
            for (int k16 = 0; k16 < 4; k16++) {
                int kel = k16 * 16;
                uint32_t ah[2][4], al[2][4];
                #pragma unroll
                for (int mt = 0; mt < 2; mt++) {
                    uint32_t ar = sb + SM_A_H
                        + (wm * 32 + mt * 16 + (lane & 15)) * A_STRIDE
                        + (ks * 64 + kel + (lane >> 4) * 8) * 2;
                    ldsm4(ah[mt], ar);
                    ldsm4(al[mt], ar + (SM_A_L - SM_A_H));
                }
                #pragma unroll
                for (int np = 0; np < 2; np++) {
                    uint32_t bh[4], bl[4];
                    uint32_t br = sb + SM_B
                        + (wn * 32 + np * 16 + (lane & 7) + (lane >> 4) * 8) * B_STRIDE
                        + (kel + ((lane >> 3) & 1) * 8) * 2;
                    ldsm4(bh, br);
                    ldsm4(bl, br + B_MAT);
                    #pragma unroll
                    for (int mt = 0; mt < 2; mt++) {
                        mma_bf16(acc[mt][np * 2 + 0], ah[mt], bh + 0);
                        mma_bf16(acc[mt][np * 2 + 1], ah[mt], bh + 2);
                        mma_bf16(acc[mt][np * 2 + 0], ah[mt], bl + 0);
                        mma_bf16(acc[mt][np * 2 + 1], ah[mt], bl + 2);
                        mma_bf16(acc[mt][np * 2 + 0], al[mt], bh + 0);
                        mma_bf16(acc[mt][np * 2 + 1], al[mt], bh + 2);
                    }
                }
            }
        }

        // --- chunk epilogue: scores + per-lane top-2 update ---
        #pragma unroll
        for (int mt = 0; mt < 2; mt++) {
            #pragma unroll
            for (int nt = 0; nt < 4; nt++) {
                int col = chunk * BN + wn * 32 + nt * 8 + (lane & 3) * 2;
                float s0 = cn_s[col]     - 2.0f * acc[mt][nt][0];
                float s1 = cn_s[col + 1] - 2.0f * acc[mt][nt][1];
                float s2 = cn_s[col]     - 2.0f * acc[mt][nt][2];
                float s3 = cn_s[col + 1] - 2.0f * acc[mt][nt][3];
                int sl0 = mt * 2, sl1 = mt * 2 + 1;
                if (s0 < bv[sl0]) { b2[sl0] = bv[sl0]; bv[sl0] = s0; bi[sl0] = col; }
                else b2[sl0] = fminf(b2[sl0], s0);
                if (s1 < bv[sl0]) { b2[sl0] = bv[sl0]; bv[sl0] = s1; bi[sl0] = col + 1; }
                else b2[sl0] = fminf(b2[sl0], s1);
                if (s2 < bv[sl1]) { b2[sl1] = bv[sl1]; bv[sl1] = s2; bi[sl1] = col; }
                else b2[sl1] = fminf(b2[sl1], s2);
                if (s3 < bv[sl1]) { b2[sl1] = bv[sl1]; bv[sl1] = s3; bi[sl1] = col + 1; }
                else b2[sl1] = fminf(b2[sl1], s3);
            }
        }
    }

    // --- cross-lane (quad) top-2 merge per row slot ---
    #pragma unroll
    for (int s = 0; s < 4; s++) {
        #pragma unroll
        for (int off = 1; off <= 2; off <<= 1) {
            float ov = __shfl_xor_sync(0xffffffffu, bv[s], off);
            float o2 = __shfl_xor_sync(0xffffffffu, b2[s], off);
            int   oi = __shfl_xor_sync(0xffffffffu, bi[s], off);
            float n2 = fminf(fminf(b2[s], o2), fmaxf(bv[s], ov));
            if (ov < bv[s] || (ov == bv[s] && oi < bi[s])) { bv[s] = ov; bi[s] = oi; }
            b2[s] = n2;
        }
    }
    __syncthreads();   // done with B buffer; reuse as merge scratch

    float* V1 = (float*)(smem + SM_B);            // [64][4]
    float* V2 = (float*)(smem + SM_B + 1024);
    int*   I1 = (int*)(smem + SM_B + 2048);
    if ((lane & 3) == 0) {
        #pragma unroll
        for (int s = 0; s < 4; s++) {
            int mt = s >> 1, hi = s & 1;
            int r = wm * 32 + mt * 16 + (lane >> 2) + hi * 8;
            V1[r * 4 + wn] = bv[s];
            V2[r * 4 + wn] = b2[s];
            I1[r * 4 + wn] = bi[s];
        }
    }
    __syncthreads();

    const long long NQ = (long long)nrows * DDIM;
    if (tid < BM) {
        float v1 = V1[tid * 4], v2 = V2[tid * 4];
        int   i1 = I1[tid * 4];
        #pragma unroll
        for (int j = 1; j < 4; j++) {
            float a1 = V1[tid * 4 + j], a2 = V2[tid * 4 + j];
            int   ai = I1[tid * 4 + j];
            float n2 = fminf(fminf(v2, a2), fmaxf(v1, a1));
            if (a1 < v1 || (a1 == v1 && ai < i1)) { v1 = a1; i1 = ai; }
            v2 = n2;
        }
        bidx_s[tid] = i1;
        long long row = row_base + tid;
        if (v2 - v1 < MARGIN) {
            int slot = atomicAdd(&g_cnt, 1);
            g_list[slot] = (int)row;
        }
        if (out_size >= NQ + nrows) out[NQ + row] = (float)i1;
        else if (out_size < NQ && row < out_size) out[row] = (float)i1;
    }
    __syncthreads();

    // --- gather quantized = codes[best] ---
    if (out_size >= NQ) {
        const float4* c4 = (const float4*)codes;
        float4* o4 = (float4*)out;
        for (int i = tid; i < BM * (DDIM / 4); i += 256) {
            int r = i >> 6;
            int q = i & 63;
            o4[(size_t)(row_base + r) * (DDIM / 4) + q] =
                c4[(size_t)bidx_s[r] * (DDIM / 4) + q];
        }
    }
}

// ---------------------------------------------------------------------------
// Refine kernel v6 (unchanged from R14 pass): 1024 threads, one code per
// thread; fp32 prefilter + FILT_EPS, fp64 exact pass, tie-window select.
// ---------------------------------------------------------------------------
__global__ void __launch_bounds__(1024)
refine_kernel(const float* __restrict__ x, const float* __restrict__ codes,
              float* __restrict__ out, long long NQ, long long out_size,
              int nrows, int C)
{
    __shared__ __align__(16) float xr[DDIM];
    __shared__ double partial[256];
    __shared__ float  fv[1024];
    __shared__ int    fi[1024];
    __shared__ int    sel;
    __shared__ float  vm_s, filt_s;

    const int t = threadIdx.x;
    int cnt = g_cnt;
    if (cnt > 65536) cnt = 65536;

    for (int w = blockIdx.x; w < cnt; w += gridDim.x) {
        int row = g_list[w];
        if (t < DDIM) xr[t] = x[(size_t)row * DDIM + t];
        __syncthreads();

        if (t < 256) partial[t] = (double)xr[t] * (double)xr[t];
        __syncthreads();
        for (int s = 128; s; s >>= 1) {
            if (t < s) partial[t] += partial[t + s];
            __syncthreads();
        }
        float s1f = (float)partial[0];

        const int c = t;
        const float4* crow = (const float4*)(codes + (size_t)c * DDIM);
        const float4* xr4  = (const float4*)xr;
        float a0 = 0.f, a1 = 0.f, a2 = 0.f, a3 = 0.f;
        #pragma unroll 8
        for (int k4 = 0; k4 < DDIM / 4; k4++) {
            float4 cv = __ldg(&crow[k4]);
            float4 xv = xr4[k4];
            a0 = fmaf(cv.x, xv.x, a0);
            a1 = fmaf(cv.y, xv.y, a1);
            a2 = fmaf(cv.z, xv.z, a2);
            a3 = fmaf(cv.w, xv.w, a3);
        }
        float dot = (a0 + a1) + (a2 + a3);
        float dv  = (s1f - 2.0f * dot) + g_cnorm[c];

        fv[t] = dv;
        __syncthreads();
        for (int s = 512; s; s >>= 1) {
            if (t < s) fv[t] = fminf(fv[t], fv[t + s]);
            __syncthreads();
        }
        if (t == 0) filt_s = fv[0] + FILT_EPS;
        __syncthreads();
        float filt = filt_s;

        float ev = 3.4e38f;
        if (dv <= filt) {
            const float* cr = codes + (size_t)c * DDIM;
            double d0 = 0.0, d1 = 0.0, d2 = 0.0, d3 = 0.0;
            #pragma unroll 4
            for (int k = 0; k < DDIM; k += 4) {
                d0 = fma((double)xr[k],     (double)__ldg(&cr[k]),     d0);
                d1 = fma((double)xr[k + 1], (double)__ldg(&cr[k + 1]), d1);
                d2 = fma((double)xr[k + 2], (double)__ldg(&cr[k + 2]), d2);
                d3 = fma((double)xr[k + 3], (double)__ldg(&cr[k + 3]), d3);
            }
            double dd = (d0 + d1) + (d2 + d3);
            float dotf = (float)dd;
            float t1   = s1f - 2.0f * dotf;
            ev = t1 + g_cnorm[c];
        }

        fv[t] = ev;
        __syncthreads();
        for (int s = 512; s; s >>= 1) {
            if (t < s) fv[t] = fminf(fv[t], fv[t + s]);
            __syncthreads();
        }
        if (t == 0) vm_s = fv[0];
        __syncthreads();
        float vm = vm_s;
        float tie_hi = __int_as_float(__float_as_int(vm) + TIE_ULPS);

        fi[t] = (ev <= tie_hi) ? c : 0x7fffffff;
        __syncthreads();
        for (int s = 512; s; s >>= 1) {
            if (t < s) fi[t] = min(fi[t], fi[t + s]);
            __syncthreads();
        }
        if (t == 0) {
            sel = fi[0];
            if (out_size >= NQ + nrows) out[NQ + row] = (float)fi[0];
            else if (out_size < NQ && row < out_size) out[row] = (float)fi[0];
        }
        __syncthreads();

        if (out_size >= NQ && t < DDIM)
            out[(size_t)row * DDIM + t] = codes[(size_t)sel * DDIM + t];
        __syncthreads();
    }
}

// ---------------------------------------------------------------------------
extern "C" void kernel_launch(void* const* d_in, const int* in_sizes, int n_in,
                              void* d_out, int out_size)
{
    const float* x     = (const float*)d_in[0];
    const float* codes = (const float*)d_in[1];
    int nrows = in_sizes[0] / DDIM;   // 65536
    int C     = in_sizes[1] / DDIM;   // 1024

    cudaFuncSetAttribute(vq_mma, cudaFuncAttributeMaxDynamicSharedMemorySize,
                         SM_TOTAL);

    prep_codes<<<C, 256>>>(codes);

    vq_mma<<<nrows / BM, 256, SM_TOTAL>>>(x, codes, (float*)d_out,
                                          (long long)out_size, nrows);

    long long NQ = (long long)nrows * DDIM;
    refine_kernel<<<1024, 1024>>>(x, codes, (float*)d_out, NQ,
                                  (long long)out_size, nrows, C);
}